// round 1
// baseline (speedup 1.0000x reference)
#include <cuda_runtime.h>

#define SB 32      // batch
#define SS 128     // source length / max_len
#define HH 512     // hidden
#define VV 32000   // vocab
#define NHD 8      // heads
#define DKD 64     // head dim
#define NSTEP 127  // decode steps (MAX_LEN-1)

// ---------------- persistent device state (no allocations allowed) ----------------
__device__ float g_h[2][2][SB][HH];      // [pingpong][layer][b][h]
__device__ float g_c[2][2][SB][HH];
__device__ float g_k[SB][SS][HH];        // precomputed K  [b][s][head*64+d]
__device__ float g_v[SB][SS][HH];        // precomputed V
__device__ float g_attn[SB][HH];         // concat attention heads
__device__ float g_attno[SB][HH];        // after Wo projection
__device__ unsigned long long g_packed[SB]; // argmax accumulator per batch row

__device__ __forceinline__ float sigf(float x) { return 1.f / (1.f + expf(-x)); }

// sortable key: max value wins; exact ties -> smallest index wins
__device__ __forceinline__ unsigned long long amax_key(float v, int n) {
    unsigned u = __float_as_uint(v);
    u = (u & 0x80000000u) ? ~u : (u | 0x80000000u);
    return ((unsigned long long)u << 32) | (unsigned)(~(unsigned)n);
}

// ---------------- init: copy h/c state, zero outputs[:,0,:] ----------------
__global__ void init_kernel(const float* __restrict__ hidden,
                            const float* __restrict__ cell,
                            float* __restrict__ out) {
    int idx = blockIdx.x * blockDim.x + threadIdx.x;
    const int nhc = 2 * SB * HH; // 32768 = g_h[0][...] flattened
    if (idx < nhc) {
        ((float*)g_h)[idx] = hidden[idx];
        ((float*)g_c)[idx] = cell[idx];
    }
    if (idx < SB * VV) {
        int b = idx / VV, v = idx % VV;
        out[(size_t)b * SS * VV + v] = 0.f;
    }
}

// ---------------- K/V projection: C[r][n] = hs[s][b][:] . W[n][:] + bias[n] ----------------
// r = b*128+s, M=4096, N=512, K=512. BM=32, BN=128, BK=32, 256 threads, 4x4 micro-tile.
__global__ void kv_kernel(const float* __restrict__ hs, const float* __restrict__ W,
                          const float* __restrict__ bias, int which) {
    __shared__ float Ash[32][36];
    __shared__ float Wsh[32][132];
    float* dst = which ? &g_v[0][0][0] : &g_k[0][0][0];
    const int r0 = blockIdx.x * 32;
    const int n0 = blockIdx.y * 128;
    const int tid = threadIdx.x;
    const int lane = tid & 31, grp = tid >> 5;
    float acc[4][4] = {};
    for (int k0 = 0; k0 < HH; k0 += 32) {
        #pragma unroll
        for (int j = 0; j < 4; j++) {
            int m = grp + j * 8;
            int r = r0 + m;
            int bb = r >> 7, s = r & 127;
            Ash[lane][m] = hs[(size_t)s * (SB * HH) + bb * HH + k0 + lane];
        }
        #pragma unroll
        for (int j = 0; j < 16; j++) {
            int nn = grp + j * 8;
            Wsh[lane][nn] = W[(size_t)(n0 + nn) * HH + k0 + lane];
        }
        __syncthreads();
        #pragma unroll
        for (int k = 0; k < 32; k++) {
            float4 a4 = *(const float4*)&Ash[k][grp * 4];
            float4 w4 = *(const float4*)&Wsh[k][lane * 4];
            acc[0][0] += a4.x * w4.x; acc[0][1] += a4.x * w4.y; acc[0][2] += a4.x * w4.z; acc[0][3] += a4.x * w4.w;
            acc[1][0] += a4.y * w4.x; acc[1][1] += a4.y * w4.y; acc[1][2] += a4.y * w4.z; acc[1][3] += a4.y * w4.w;
            acc[2][0] += a4.z * w4.x; acc[2][1] += a4.z * w4.y; acc[2][2] += a4.z * w4.z; acc[2][3] += a4.z * w4.w;
            acc[3][0] += a4.w * w4.x; acc[3][1] += a4.w * w4.y; acc[3][2] += a4.w * w4.z; acc[3][3] += a4.w * w4.w;
        }
        __syncthreads();
    }
    const int nbase = n0 + lane * 4;
    float4 b4 = *(const float4*)&bias[nbase];
    #pragma unroll
    for (int i = 0; i < 4; i++) {
        int r = r0 + grp * 4 + i;
        float4 v;
        v.x = acc[i][0] + b4.x; v.y = acc[i][1] + b4.y;
        v.z = acc[i][2] + b4.z; v.w = acc[i][3] + b4.w;
        *(float4*)&dst[(size_t)r * HH + nbase] = v;
    }
}

// ---------------- LSTM layer: one warp per gate-quad (i,f,g,o of one hidden dim) ----------------
// 128 blocks x 128 threads; warp -> n' = blockIdx*4+warp (512 total); lane = batch.
// Fuses embedding gather (layer 0), argmax-token decode, GEMM and activation.
__global__ void lstm_kernel(int layer, int pin, int first,
                            const float* __restrict__ emb,
                            const float* __restrict__ W_ih, const float* __restrict__ W_hh,
                            const float* __restrict__ b_ih, const float* __restrict__ b_hh) {
    __shared__ float As[SB][129];   // chunk of concat input [x|h], [32][128]
    __shared__ int tok_s[SB];
    const int tid = threadIdx.x;
    const int lane = tid & 31, warp = tid >> 5;
    const int pout = pin ^ 1;
    if (tid < SB)
        tok_s[tid] = first ? 0 : (int)(~(unsigned)(g_packed[tid] & 0xFFFFFFFFull));
    const int np = blockIdx.x * 4 + warp;  // hidden index 0..511
    const float* Wih = W_ih + (size_t)layer * 4 * HH * HH;
    const float* Whh = W_hh + (size_t)layer * 4 * HH * HH;
    float ai = 0.f, af = 0.f, ag = 0.f, ao = 0.f;
    for (int c = 0; c < 8; c++) {           // K=1024 in chunks of 128
        __syncthreads();
        #pragma unroll
        for (int j = 0; j < 32; j++) {
            int e = tid + j * 128;          // 0..4095
            int b = e >> 7, kk = e & 127;
            int kg = c * 128 + kk;
            float v;
            if (kg < HH) {
                v = (layer == 0) ? emb[(size_t)tok_s[b] * HH + kg]
                                 : g_h[pout][0][b][kg];
            } else {
                v = g_h[pin][layer][b][kg - HH];
            }
            As[b][kk] = v;
        }
        __syncthreads();
        const float* Wsrc = (c < 4) ? Wih : Whh;
        int koff = (c < 4) ? c * 128 : (c - 4) * 128;
        const float4* wri = (const float4*)(Wsrc + (size_t)(np) * HH + koff);
        const float4* wrf = (const float4*)(Wsrc + (size_t)(HH + np) * HH + koff);
        const float4* wrg = (const float4*)(Wsrc + (size_t)(2 * HH + np) * HH + koff);
        const float4* wro = (const float4*)(Wsrc + (size_t)(3 * HH + np) * HH + koff);
        #pragma unroll 8
        for (int k4 = 0; k4 < 32; k4++) {
            float4 wi = wri[k4], wf = wrf[k4], wg = wrg[k4], wo = wro[k4];
            int kk = k4 * 4;
            float a0 = As[lane][kk + 0], a1 = As[lane][kk + 1];
            float a2 = As[lane][kk + 2], a3 = As[lane][kk + 3];
            ai += a0 * wi.x + a1 * wi.y + a2 * wi.z + a3 * wi.w;
            af += a0 * wf.x + a1 * wf.y + a2 * wf.z + a3 * wf.w;
            ag += a0 * wg.x + a1 * wg.y + a2 * wg.z + a3 * wg.w;
            ao += a0 * wo.x + a1 * wo.y + a2 * wo.z + a3 * wo.w;
        }
    }
    const size_t bb = (size_t)layer * 4 * HH;
    ai += b_ih[bb + np]          + b_hh[bb + np];
    af += b_ih[bb + HH + np]     + b_hh[bb + HH + np];
    ag += b_ih[bb + 2 * HH + np] + b_hh[bb + 2 * HH + np];
    ao += b_ih[bb + 3 * HH + np] + b_hh[bb + 3 * HH + np];
    int b = lane;
    float cold = g_c[pin][layer][b][np];
    float cn = sigf(af) * cold + sigf(ai) * tanhf(ag);
    float hn = sigf(ao) * tanhf(cn);
    g_c[pout][layer][b][np] = cn;
    g_h[pout][layer][b][np] = hn;
}

// ---------------- attention: one block per (b, head); q proj + softmax + AV fused ----------------
__global__ void attn_kernel(int pout, const float* __restrict__ Wq, const float* __restrict__ bq) {
    const int b = blockIdx.x, hd = blockIdx.y;
    __shared__ float sx[HH];
    __shared__ float qs[DKD];
    __shared__ float ps[SS];
    __shared__ float red[4];
    __shared__ float red2[4];
    const int tid = threadIdx.x;          // 128
    const int lane = tid & 31, warp = tid >> 5;
    for (int i = tid; i < HH; i += 128) sx[i] = g_h[pout][1][b][i];
    __syncthreads();
    // q[j] via warp-reduced dot products (coalesced Wq reads)
    for (int jj = 0; jj < 16; jj++) {
        int j = warp * 16 + jj;
        const float* wr = Wq + (size_t)(hd * DKD + j) * HH;
        float s = 0.f;
        for (int k = lane; k < HH; k += 32) s += sx[k] * wr[k];
        #pragma unroll
        for (int off = 16; off; off >>= 1) s += __shfl_xor_sync(0xffffffffu, s, off);
        if (lane == 0) qs[j] = s + bq[hd * DKD + j];
    }
    __syncthreads();
    {   // scores: thread = source position s
        const float* kr = &g_k[b][tid][hd * DKD];
        float acc = 0.f;
        #pragma unroll 16
        for (int d = 0; d < DKD; d++) acc += qs[d] * kr[d];
        ps[tid] = acc * 0.125f;           // 1/sqrt(64)
    }
    __syncthreads();
    float m = ps[tid];
    #pragma unroll
    for (int off = 16; off; off >>= 1) m = fmaxf(m, __shfl_xor_sync(0xffffffffu, m, off));
    if (lane == 0) red[warp] = m;
    __syncthreads();
    m = fmaxf(fmaxf(red[0], red[1]), fmaxf(red[2], red[3]));
    float ev = expf(ps[tid] - m);
    float sum = ev;
    #pragma unroll
    for (int off = 16; off; off >>= 1) sum += __shfl_xor_sync(0xffffffffu, sum, off);
    if (lane == 0) red2[warp] = sum;
    __syncthreads();
    float total = red2[0] + red2[1] + red2[2] + red2[3];
    ps[tid] = ev;
    __syncthreads();
    if (tid < DKD) {
        float acc = 0.f;
        for (int s = 0; s < SS; s++) acc += ps[s] * g_v[b][s][hd * DKD + tid];
        g_attn[b][hd * DKD + tid] = acc / total;
    }
}

// ---------------- Wo projection; also resets argmax accumulators for this step ----------------
__global__ void wo_kernel(const float* __restrict__ Wo, const float* __restrict__ bo) {
    __shared__ float As[SB][129];
    const int tid = threadIdx.x;          // 128
    const int lane = tid & 31, warp = tid >> 5;
    if (blockIdx.x == 0 && tid < SB) g_packed[tid] = 0ull;
    const int n = blockIdx.x * 4 + warp;  // 0..511
    float acc = 0.f;
    for (int c = 0; c < 4; c++) {
        __syncthreads();
        #pragma unroll
        for (int j = 0; j < 32; j++) {
            int e = tid + j * 128;
            int b = e >> 7, kk = e & 127;
            As[b][kk] = g_attn[b][c * 128 + kk];
        }
        __syncthreads();
        const float4* wr = (const float4*)(Wo + (size_t)n * HH + c * 128);
        #pragma unroll 8
        for (int k4 = 0; k4 < 32; k4++) {
            float4 w = wr[k4];
            int kk = k4 * 4;
            acc += As[lane][kk] * w.x + As[lane][kk + 1] * w.y
                 + As[lane][kk + 2] * w.z + As[lane][kk + 3] * w.w;
        }
    }
    g_attno[lane][n] = acc + bo[n];
}

// ---------------- logits GEMM [32,512]x[512,32000] + bias + store + fused argmax ----------------
__global__ void logits_kernel(const float* __restrict__ Wout, const float* __restrict__ bout,
                              float* __restrict__ out, int t) {
    __shared__ float Ash[32][36];
    __shared__ float Wsh[32][132];
    const int n0 = blockIdx.x * 128;
    const int tid = threadIdx.x;          // 256
    const int lane = tid & 31, grp = tid >> 5;
    float acc[4][4] = {};
    for (int k0 = 0; k0 < HH; k0 += 32) {
        #pragma unroll
        for (int j = 0; j < 4; j++) {
            int m = grp + j * 8;
            Ash[lane][m] = g_attno[m][k0 + lane];
        }
        #pragma unroll
        for (int j = 0; j < 16; j++) {
            int nn = grp + j * 8;
            Wsh[lane][nn] = Wout[(size_t)(n0 + nn) * HH + k0 + lane];
        }
        __syncthreads();
        #pragma unroll
        for (int k = 0; k < 32; k++) {
            float4 a4 = *(const float4*)&Ash[k][grp * 4];
            float4 w4 = *(const float4*)&Wsh[k][lane * 4];
            acc[0][0] += a4.x * w4.x; acc[0][1] += a4.x * w4.y; acc[0][2] += a4.x * w4.z; acc[0][3] += a4.x * w4.w;
            acc[1][0] += a4.y * w4.x; acc[1][1] += a4.y * w4.y; acc[1][2] += a4.y * w4.z; acc[1][3] += a4.y * w4.w;
            acc[2][0] += a4.z * w4.x; acc[2][1] += a4.z * w4.y; acc[2][2] += a4.z * w4.z; acc[2][3] += a4.z * w4.w;
            acc[3][0] += a4.w * w4.x; acc[3][1] += a4.w * w4.y; acc[3][2] += a4.w * w4.z; acc[3][3] += a4.w * w4.w;
        }
        __syncthreads();
    }
    const int nbase = n0 + lane * 4;
    float4 b4 = *(const float4*)&bout[nbase];
    #pragma unroll
    for (int i = 0; i < 4; i++) {
        int b = grp * 4 + i;              // warp == grp -> all lanes share b
        float4 v;
        v.x = acc[i][0] + b4.x; v.y = acc[i][1] + b4.y;
        v.z = acc[i][2] + b4.z; v.w = acc[i][3] + b4.w;
        *(float4*)&out[((size_t)b * SS + t + 1) * VV + nbase] = v;
        unsigned long long best = amax_key(v.x, nbase);
        unsigned long long k1 = amax_key(v.y, nbase + 1); if (k1 > best) best = k1;
        unsigned long long k2 = amax_key(v.z, nbase + 2); if (k2 > best) best = k2;
        unsigned long long k3 = amax_key(v.w, nbase + 3); if (k3 > best) best = k3;
        #pragma unroll
        for (int off = 16; off; off >>= 1) {
            unsigned long long o = __shfl_xor_sync(0xffffffffu, best, off);
            if (o > best) best = o;
        }
        if (lane == 0) atomicMax(&g_packed[b], best);
    }
}

// ---------------- launch sequence (graph-capturable: kernels only) ----------------
extern "C" void kernel_launch(void* const* d_in, const int* in_sizes, int n_in,
                              void* d_out, int out_size) {
    const float* hs     = (const float*)d_in[0];
    const float* hidden = (const float*)d_in[1];
    const float* cell   = (const float*)d_in[2];
    const float* emb    = (const float*)d_in[3];
    const float* W_ih   = (const float*)d_in[4];
    const float* W_hh   = (const float*)d_in[5];
    const float* b_ih   = (const float*)d_in[6];
    const float* b_hh   = (const float*)d_in[7];
    const float* Wq     = (const float*)d_in[8];
    const float* bq     = (const float*)d_in[9];
    const float* Wk     = (const float*)d_in[10];
    const float* bk     = (const float*)d_in[11];
    const float* Wv     = (const float*)d_in[12];
    const float* bv     = (const float*)d_in[13];
    const float* Wo     = (const float*)d_in[14];
    const float* bo     = (const float*)d_in[15];
    const float* W_out  = (const float*)d_in[16];
    const float* b_out  = (const float*)d_in[17];
    float* out = (float*)d_out;

    init_kernel<<<4000, 256>>>(hidden, cell, out);

    dim3 kvg(128, 4); // 4096/32 row tiles x 512/128 col tiles
    kv_kernel<<<kvg, 256>>>(hs, Wk, bk, 0);
    kv_kernel<<<kvg, 256>>>(hs, Wv, bv, 1);

    for (int t = 0; t < NSTEP; t++) {
        int pin = t & 1;
        lstm_kernel<<<128, 128>>>(0, pin, (t == 0) ? 1 : 0, emb, W_ih, W_hh, b_ih, b_hh);
        lstm_kernel<<<128, 128>>>(1, pin, 0, emb, W_ih, W_hh, b_ih, b_hh);
        attn_kernel<<<dim3(SB, NHD), 128>>>(pin ^ 1, Wq, bq);
        wo_kernel<<<128, 128>>>(Wo, bo);
        logits_kernel<<<250, 256>>>(W_out, b_out, out, t);
    }
}

// round 2
// speedup vs baseline: 1.4022x; 1.4022x over previous
#include <cuda_runtime.h>

#define SB 32      // batch
#define SS 128     // source length / max_len
#define HH 512     // hidden
#define VV 32000   // vocab
#define NSTEP 127  // decode steps

// ---------------- persistent device state ----------------
__device__ float g_h[2][2][HH][SB];          // [pingpong][layer][dim][b]  (transposed!)
__device__ float g_c[2][2][HH][SB];
__device__ float g_k[SB][SS][HH];            // K [b][s][head*64+d]
__device__ float g_v[SB][SS][HH];            // V
__device__ float g_gpart[2][4][HH][SB];      // LSTM gate partials [ksplit][gate][np][b]
__device__ float g_attno[SB][HH];            // attention output after Wo
__device__ unsigned long long g_packed[SB];  // argmax accumulator

__device__ __forceinline__ float sigf(float x) { return 1.f / (1.f + expf(-x)); }

__device__ __forceinline__ unsigned long long amax_key(float v, int n) {
    unsigned u = __float_as_uint(v);
    u = (u & 0x80000000u) ? ~u : (u | 0x80000000u);
    return ((unsigned long long)u << 32) | (unsigned)(~(unsigned)n);
}

// ---------------- init: transpose h/c state, zero outputs[:,0,:] ----------------
__global__ void init_kernel(const float* __restrict__ hidden,
                            const float* __restrict__ cell,
                            float* __restrict__ out) {
    int idx = blockIdx.x * blockDim.x + threadIdx.x;
    const int nhc = 2 * SB * HH;
    if (idx < nhc) {
        int l = idx >> 14, b = (idx >> 9) & 31, h = idx & 511;
        g_h[0][l][h][b] = hidden[idx];
        g_c[0][l][h][b] = cell[idx];
    }
    if (idx < SB * VV) {
        int b = idx / VV, v = idx % VV;
        out[(size_t)b * SS * VV + v] = 0.f;
    }
}

// ---------------- K/V projection (one-time): C[r][n] = hs . W^T + bias ----------------
__global__ void kv_kernel(const float* __restrict__ hs, const float* __restrict__ W,
                          const float* __restrict__ bias, int which) {
    __shared__ float Ash[32][36];
    __shared__ float Wsh[32][132];
    float* dst = which ? &g_v[0][0][0] : &g_k[0][0][0];
    const int r0 = blockIdx.x * 32;
    const int n0 = blockIdx.y * 128;
    const int tid = threadIdx.x;
    const int lane = tid & 31, grp = tid >> 5;
    float acc[4][4] = {};
    for (int k0 = 0; k0 < HH; k0 += 32) {
        #pragma unroll
        for (int j = 0; j < 4; j++) {
            int m = grp + j * 8;
            int r = r0 + m;
            int bb = r >> 7, s = r & 127;
            Ash[lane][m] = hs[(size_t)s * (SB * HH) + bb * HH + k0 + lane];
        }
        #pragma unroll
        for (int j = 0; j < 16; j++) {
            int nn = grp + j * 8;
            Wsh[lane][nn] = W[(size_t)(n0 + nn) * HH + k0 + lane];
        }
        __syncthreads();
        #pragma unroll
        for (int k = 0; k < 32; k++) {
            float4 a4 = *(const float4*)&Ash[k][grp * 4];
            float4 w4 = *(const float4*)&Wsh[k][lane * 4];
            acc[0][0] += a4.x * w4.x; acc[0][1] += a4.x * w4.y; acc[0][2] += a4.x * w4.z; acc[0][3] += a4.x * w4.w;
            acc[1][0] += a4.y * w4.x; acc[1][1] += a4.y * w4.y; acc[1][2] += a4.y * w4.z; acc[1][3] += a4.y * w4.w;
            acc[2][0] += a4.z * w4.x; acc[2][1] += a4.z * w4.y; acc[2][2] += a4.z * w4.z; acc[2][3] += a4.z * w4.w;
            acc[3][0] += a4.w * w4.x; acc[3][1] += a4.w * w4.y; acc[3][2] += a4.w * w4.z; acc[3][3] += a4.w * w4.w;
        }
        __syncthreads();
    }
    const int nbase = n0 + lane * 4;
    float4 b4 = *(const float4*)&bias[nbase];
    #pragma unroll
    for (int i = 0; i < 4; i++) {
        int r = r0 + grp * 4 + i;
        float4 v;
        v.x = acc[i][0] + b4.x; v.y = acc[i][1] + b4.y;
        v.z = acc[i][2] + b4.z; v.w = acc[i][3] + b4.w;
        *(float4*)&dst[(size_t)r * HH + nbase] = v;
    }
}

// ---------------- LSTM GEMM: grid(64 ntiles, 2 ksplits) x 256 thr ----------------
// ks=0: x @ W_ih  (x = emb gather for layer0, h[layer0-out] for layer1), K=512
// ks=1: h_prev @ W_hh, K=512
// Block tile: 32 batches x 32 rows (8 np x 4 gates). Micro 2x2. Reg-prefetched.
__global__ void lstm_gemm(int layer, int pin, int first, const float* __restrict__ emb,
                          const float* __restrict__ W_ih, const float* __restrict__ W_hh) {
    __shared__ float Ash[32][34];
    __shared__ float Wsh[32][34];
    __shared__ int tok_s[SB];
    const int tid = threadIdx.x;
    const int ks = blockIdx.y;
    const int np0 = blockIdx.x * 8;
    const int pout = pin ^ 1;
    const int lane = tid & 31, w = tid >> 5;
    const int tb = tid & 15, tn = tid >> 4;

    if (tid < SB)
        tok_s[tid] = first ? 0 : (int)(~(unsigned)(g_packed[tid] & 0xFFFFFFFFull));
    __syncthreads();

    const float* W = ((ks == 0) ? W_ih : W_hh) + (size_t)layer * 4 * HH * HH;
    const bool emb_path = (ks == 0 && layer == 0);
    const float* xsrc = (ks == 0) ? &g_h[pout][0][0][0] : &g_h[pin][layer][0][0];

    float ra[4], rw[4];
    // fetch chunk 0
    {
        const int k0 = 0;
        if (emb_path) {
            #pragma unroll
            for (int i = 0; i < 4; i++)
                ra[i] = emb[(size_t)tok_s[w * 4 + i] * HH + k0 + lane];
        } else {
            #pragma unroll
            for (int j = 0; j < 4; j++) {
                int e = tid + j * 256;
                ra[j] = xsrc[(size_t)(k0 + (e >> 5)) * SB + (e & 31)];
            }
        }
        #pragma unroll
        for (int j = 0; j < 4; j++) {
            int e = tid + j * 256;
            int nl = e >> 5, kk = e & 31;
            int g = nl >> 3, np = np0 + (nl & 7);
            rw[j] = W[(size_t)(g * HH + np) * HH + k0 + kk];
        }
    }

    float acc[2][2] = {};
    for (int c = 0; c < 16; c++) {
        // store staged regs to smem
        if (emb_path) {
            #pragma unroll
            for (int i = 0; i < 4; i++) Ash[lane][w * 4 + i] = ra[i];
        } else {
            #pragma unroll
            for (int j = 0; j < 4; j++) {
                int e = tid + j * 256;
                Ash[e >> 5][e & 31] = ra[j];
            }
        }
        #pragma unroll
        for (int j = 0; j < 4; j++) {
            int e = tid + j * 256;
            Wsh[e & 31][e >> 5] = rw[j];
        }
        __syncthreads();
        // prefetch next chunk
        if (c < 15) {
            const int k0 = (c + 1) * 32;
            if (emb_path) {
                #pragma unroll
                for (int i = 0; i < 4; i++)
                    ra[i] = emb[(size_t)tok_s[w * 4 + i] * HH + k0 + lane];
            } else {
                #pragma unroll
                for (int j = 0; j < 4; j++) {
                    int e = tid + j * 256;
                    ra[j] = xsrc[(size_t)(k0 + (e >> 5)) * SB + (e & 31)];
                }
            }
            #pragma unroll
            for (int j = 0; j < 4; j++) {
                int e = tid + j * 256;
                int nl = e >> 5, kk = e & 31;
                int g = nl >> 3, np = np0 + (nl & 7);
                rw[j] = W[(size_t)(g * HH + np) * HH + k0 + kk];
            }
        }
        // compute
        #pragma unroll
        for (int k = 0; k < 32; k++) {
            float2 a2 = *(const float2*)&Ash[k][tb * 2];
            float2 w2 = *(const float2*)&Wsh[k][tn * 2];
            acc[0][0] += a2.x * w2.x; acc[0][1] += a2.x * w2.y;
            acc[1][0] += a2.y * w2.x; acc[1][1] += a2.y * w2.y;
        }
        __syncthreads();
    }
    #pragma unroll
    for (int j = 0; j < 2; j++) {
        int nl = tn * 2 + j;
        int g = nl >> 3, np = np0 + (nl & 7);
        #pragma unroll
        for (int i = 0; i < 2; i++)
            g_gpart[ks][g][np][tb * 2 + i] = acc[i][j];
    }
}

// ---------------- LSTM activation: sum partials + biases, apply gates ----------------
__global__ void lstm_act(int layer, int pin,
                         const float* __restrict__ b_ih, const float* __restrict__ b_hh) {
    const int idx = blockIdx.x * blockDim.x + threadIdx.x;   // 64*256 = 16384
    const int b = idx & 31, np = idx >> 5;
    const int pout = pin ^ 1;
    const float* bi = b_ih + (size_t)layer * 4 * HH;
    const float* bh = b_hh + (size_t)layer * 4 * HH;
    float s[4];
    #pragma unroll
    for (int g = 0; g < 4; g++)
        s[g] = g_gpart[0][g][np][b] + g_gpart[1][g][np][b]
             + bi[g * HH + np] + bh[g * HH + np];
    float cold = g_c[pin][layer][np][b];
    float cn = sigf(s[1]) * cold + sigf(s[0]) * tanhf(s[2]);
    float hn = sigf(s[3]) * tanhf(cn);
    g_c[pout][layer][np][b] = cn;
    g_h[pout][layer][np][b] = hn;
}

// ---------------- fused attention + Wo: one block per batch, 512 threads ----------------
__global__ void attnwo_kernel(int pout,
                              const float* __restrict__ Wq, const float* __restrict__ bq,
                              const float* __restrict__ Wo, const float* __restrict__ bo) {
    const int b = blockIdx.x;
    __shared__ float sx[HH];
    __shared__ float qs[HH];
    __shared__ float sc[8][SS];
    __shared__ float ax[HH];
    __shared__ float tot[8];
    const int tid = threadIdx.x;               // 512
    const int lane = tid & 31, w = tid >> 5;   // 16 warps
    if (tid == 0) g_packed[b] = 0ull;          // reset argmax accumulator for this step
    sx[tid] = g_h[pout][1][tid][b];
    __syncthreads();
    // q projection: warp w computes q dims [w*32, w*32+32)
    for (int jj = 0; jj < 32; jj++) {
        int j = w * 32 + jj;
        const float* wr = Wq + (size_t)j * HH;
        float s = 0.f;
        #pragma unroll 4
        for (int k = lane; k < HH; k += 32) s += sx[k] * wr[k];
        #pragma unroll
        for (int off = 16; off; off >>= 1) s += __shfl_xor_sync(0xffffffffu, s, off);
        if (lane == 0) qs[j] = s + bq[j];
    }
    __syncthreads();
    // scores: thread -> (hd, s)
    #pragma unroll
    for (int i = 0; i < 2; i++) {
        int idx = tid + i * 512;
        int hd = idx >> 7, s = idx & 127;
        const float* kr = &g_k[b][s][hd * 64];
        const float* qr = &qs[hd * 64];
        float acc = 0.f;
        #pragma unroll 16
        for (int d = 0; d < 64; d++) acc += qr[d] * kr[d];
        sc[hd][s] = acc * 0.125f;
    }
    __syncthreads();
    // softmax per head: warp w<8 handles head w
    if (w < 8) {
        float v0 = sc[w][lane], v1 = sc[w][lane + 32];
        float v2 = sc[w][lane + 64], v3 = sc[w][lane + 96];
        float m = fmaxf(fmaxf(v0, v1), fmaxf(v2, v3));
        #pragma unroll
        for (int off = 16; off; off >>= 1) m = fmaxf(m, __shfl_xor_sync(0xffffffffu, m, off));
        float e0 = expf(v0 - m), e1 = expf(v1 - m), e2 = expf(v2 - m), e3 = expf(v3 - m);
        float s = (e0 + e1) + (e2 + e3);
        #pragma unroll
        for (int off = 16; off; off >>= 1) s += __shfl_xor_sync(0xffffffffu, s, off);
        sc[w][lane] = e0; sc[w][lane + 32] = e1; sc[w][lane + 64] = e2; sc[w][lane + 96] = e3;
        if (lane == 0) tot[w] = s;
    }
    __syncthreads();
    // AV: thread per output dim (coalesced over g_v rows)
    {
        int hd = tid >> 6;
        float acc = 0.f;
        #pragma unroll 8
        for (int s = 0; s < SS; s++) acc += sc[hd][s] * g_v[b][s][tid];
        ax[tid] = acc / tot[hd];
    }
    __syncthreads();
    // Wo: warp w computes out dims [w*32, w*32+32)
    for (int jj = 0; jj < 32; jj++) {
        int j = w * 32 + jj;
        const float* wr = Wo + (size_t)j * HH;
        float s = 0.f;
        #pragma unroll 4
        for (int k = lane; k < HH; k += 32) s += ax[k] * wr[k];
        #pragma unroll
        for (int off = 16; off; off >>= 1) s += __shfl_xor_sync(0xffffffffu, s, off);
        if (lane == 0) g_attno[b][j] = s + bo[j];
    }
}

// ---------------- logits GEMM [32,512]x[512,32000] + bias + argmax (reg-prefetched) ----------------
__global__ void logits_kernel(const float* __restrict__ Wout, const float* __restrict__ bout,
                              float* __restrict__ out, int t) {
    __shared__ float Ash[32][36];
    __shared__ float Wsh[32][132];
    const int n0 = blockIdx.x * 128;
    const int tid = threadIdx.x;          // 256
    const int lane = tid & 31, grp = tid >> 5;
    float ra[4], rw[16];
    {
        #pragma unroll
        for (int j = 0; j < 4; j++) ra[j] = g_attno[grp + j * 8][lane];
        #pragma unroll
        for (int j = 0; j < 16; j++)
            rw[j] = Wout[(size_t)(n0 + grp + j * 8) * HH + lane];
    }
    float acc[4][4] = {};
    for (int c = 0; c < 16; c++) {
        #pragma unroll
        for (int j = 0; j < 4; j++) Ash[lane][grp + j * 8] = ra[j];
        #pragma unroll
        for (int j = 0; j < 16; j++) Wsh[lane][grp + j * 8] = rw[j];
        __syncthreads();
        if (c < 15) {
            const int k0 = (c + 1) * 32;
            #pragma unroll
            for (int j = 0; j < 4; j++) ra[j] = g_attno[grp + j * 8][k0 + lane];
            #pragma unroll
            for (int j = 0; j < 16; j++)
                rw[j] = Wout[(size_t)(n0 + grp + j * 8) * HH + k0 + lane];
        }
        #pragma unroll
        for (int k = 0; k < 32; k++) {
            float4 a4 = *(const float4*)&Ash[k][grp * 4];
            float4 w4 = *(const float4*)&Wsh[k][lane * 4];
            acc[0][0] += a4.x * w4.x; acc[0][1] += a4.x * w4.y; acc[0][2] += a4.x * w4.z; acc[0][3] += a4.x * w4.w;
            acc[1][0] += a4.y * w4.x; acc[1][1] += a4.y * w4.y; acc[1][2] += a4.y * w4.z; acc[1][3] += a4.y * w4.w;
            acc[2][0] += a4.z * w4.x; acc[2][1] += a4.z * w4.y; acc[2][2] += a4.z * w4.z; acc[2][3] += a4.z * w4.w;
            acc[3][0] += a4.w * w4.x; acc[3][1] += a4.w * w4.y; acc[3][2] += a4.w * w4.z; acc[3][3] += a4.w * w4.w;
        }
        __syncthreads();
    }
    const int nbase = n0 + lane * 4;
    float4 b4 = *(const float4*)&bout[nbase];
    #pragma unroll
    for (int i = 0; i < 4; i++) {
        int b = grp * 4 + i;
        float4 v;
        v.x = acc[i][0] + b4.x; v.y = acc[i][1] + b4.y;
        v.z = acc[i][2] + b4.z; v.w = acc[i][3] + b4.w;
        *(float4*)&out[((size_t)b * SS + t + 1) * VV + nbase] = v;
        unsigned long long best = amax_key(v.x, nbase);
        unsigned long long k1 = amax_key(v.y, nbase + 1); if (k1 > best) best = k1;
        unsigned long long k2 = amax_key(v.z, nbase + 2); if (k2 > best) best = k2;
        unsigned long long k3 = amax_key(v.w, nbase + 3); if (k3 > best) best = k3;
        #pragma unroll
        for (int off = 16; off; off >>= 1) {
            unsigned long long o = __shfl_xor_sync(0xffffffffu, best, off);
            if (o > best) best = o;
        }
        if (lane == 0) atomicMax(&g_packed[b], best);
    }
}

// ---------------- launch sequence ----------------
extern "C" void kernel_launch(void* const* d_in, const int* in_sizes, int n_in,
                              void* d_out, int out_size) {
    const float* hs     = (const float*)d_in[0];
    const float* hidden = (const float*)d_in[1];
    const float* cell   = (const float*)d_in[2];
    const float* emb    = (const float*)d_in[3];
    const float* W_ih   = (const float*)d_in[4];
    const float* W_hh   = (const float*)d_in[5];
    const float* b_ih   = (const float*)d_in[6];
    const float* b_hh   = (const float*)d_in[7];
    const float* Wq     = (const float*)d_in[8];
    const float* bq     = (const float*)d_in[9];
    const float* Wk     = (const float*)d_in[10];
    const float* bk     = (const float*)d_in[11];
    const float* Wv     = (const float*)d_in[12];
    const float* bv     = (const float*)d_in[13];
    const float* Wo     = (const float*)d_in[14];
    const float* bo     = (const float*)d_in[15];
    const float* W_out  = (const float*)d_in[16];
    const float* b_out  = (const float*)d_in[17];
    float* out = (float*)d_out;

    init_kernel<<<4000, 256>>>(hidden, cell, out);

    dim3 kvg(128, 4);
    kv_kernel<<<kvg, 256>>>(hs, Wk, bk, 0);
    kv_kernel<<<kvg, 256>>>(hs, Wv, bv, 1);

    dim3 lg(64, 2);
    for (int t = 0; t < NSTEP; t++) {
        int pin = t & 1;
        lstm_gemm<<<lg, 256>>>(0, pin, (t == 0) ? 1 : 0, emb, W_ih, W_hh);
        lstm_act<<<64, 256>>>(0, pin, b_ih, b_hh);
        lstm_gemm<<<lg, 256>>>(1, pin, 0, emb, W_ih, W_hh);
        lstm_act<<<64, 256>>>(1, pin, b_ih, b_hh);
        attnwo_kernel<<<SB, 512>>>(pin ^ 1, Wq, bq, Wo, bo);
        logits_kernel<<<250, 256>>>(W_out, b_out, out, t);
    }
}

// round 5
// speedup vs baseline: 1.4094x; 1.0051x over previous
#include <cuda_runtime.h>
#include <cuda_bf16.h>
#include <cstdint>

#define SB 32      // batch
#define SS 128     // source length / max_len
#define HH 512     // hidden
#define VV 32000   // vocab
#define NSTEP 127  // decode steps

// ---------------- persistent device state ----------------
__device__ float g_h[2][2][HH][SB];          // [pingpong][layer][dim][b]
__device__ float g_c[2][2][HH][SB];
__device__ float g_k[SB][SS][HH];
__device__ float g_v[SB][SS][HH];
__device__ float g_gpart[4][4][HH][SB];      // LSTM gate partials [ksplit][gate][np][b]
__device__ float g_attno[SB][HH];
__device__ unsigned long long g_packed[SB];
__device__ __nv_bfloat16 g_wh[(size_t)VV * HH];   // W_out hi-split (bf16)
__device__ __nv_bfloat16 g_wl[(size_t)VV * HH];   // W_out lo-split (bf16)

__device__ __forceinline__ float sigf(float x) { return 1.f / (1.f + expf(-x)); }

__device__ __forceinline__ unsigned long long amax_key(float v, int n) {
    unsigned u = __float_as_uint(v);
    u = (u & 0x80000000u) ? ~u : (u | 0x80000000u);
    return ((unsigned long long)u << 32) | (unsigned)(~(unsigned)n);
}

__device__ __forceinline__ uint32_t smem_u32(const void* p) {
    uint32_t a;
    asm("{ .reg .u64 t; cvta.to.shared.u64 t, %1; cvt.u32.u64 %0, t; }" : "=r"(a) : "l"(p));
    return a;
}
__device__ __forceinline__ void ldsm_x4(uint32_t* r, uint32_t addr) {
    asm volatile("ldmatrix.sync.aligned.m8n8.x4.shared.b16 {%0,%1,%2,%3}, [%4];"
                 : "=r"(r[0]), "=r"(r[1]), "=r"(r[2]), "=r"(r[3]) : "r"(addr));
}
__device__ __forceinline__ void ldsm_x2(uint32_t* r, uint32_t addr) {
    asm volatile("ldmatrix.sync.aligned.m8n8.x2.shared.b16 {%0,%1}, [%2];"
                 : "=r"(r[0]), "=r"(r[1]) : "r"(addr));
}
__device__ __forceinline__ void mma_bf16(float* c, const uint32_t* a, const uint32_t* b) {
    asm volatile(
        "mma.sync.aligned.m16n8k16.row.col.f32.bf16.bf16.f32 "
        "{%0,%1,%2,%3}, {%4,%5,%6,%7}, {%8,%9}, {%0,%1,%2,%3};"
        : "+f"(c[0]), "+f"(c[1]), "+f"(c[2]), "+f"(c[3])
        : "r"(a[0]), "r"(a[1]), "r"(a[2]), "r"(a[3]), "r"(b[0]), "r"(b[1]));
}

#define ASTRIDE 520      // bf16 elements per A row (pad: 1040B -> 4-bank stagger)
#define BSTRIDE 72       // bf16 elements per B row (pad: 144B -> 4-bank stagger)
#define BOFF (2 * 32 * ASTRIDE * 2)                       // 66560 bytes
#define L_SMEM_TOTAL (BOFF + 2 * 128 * BSTRIDE * 2)       // 103424 bytes

// ---------------- init: state transpose, zero out[:,0,:], W_out bf16 split ----------------
__global__ void init_kernel(const float* __restrict__ hidden,
                            const float* __restrict__ cell,
                            const float* __restrict__ W_out,
                            float* __restrict__ out) {
    int idx = blockIdx.x * blockDim.x + threadIdx.x;
    const int nhc = 2 * SB * HH;
    if (idx < nhc) {
        int l = idx >> 14, b = (idx >> 9) & 31, h = idx & 511;
        g_h[0][l][h][b] = hidden[idx];
        g_c[0][l][h][b] = cell[idx];
    }
    if (idx < SB * VV) {
        int b = idx / VV, v = idx % VV;
        out[(size_t)b * SS * VV + v] = 0.f;
    }
    const size_t nw = (size_t)VV * HH;
    const size_t stride = (size_t)gridDim.x * blockDim.x;
    for (size_t i = idx; i < nw; i += stride) {
        float w = W_out[i];
        __nv_bfloat16 h = __float2bfloat16(w);
        g_wh[i] = h;
        g_wl[i] = __float2bfloat16(w - __bfloat162float(h));
    }
}

// ---------------- K/V projection (one-time) ----------------
__global__ void kv_kernel(const float* __restrict__ hs, const float* __restrict__ W,
                          const float* __restrict__ bias, int which) {
    __shared__ float Ash[32][36];
    __shared__ float Wsh[32][132];
    float* dst = which ? &g_v[0][0][0] : &g_k[0][0][0];
    const int r0 = blockIdx.x * 32;
    const int n0 = blockIdx.y * 128;
    const int tid = threadIdx.x;
    const int lane = tid & 31, grp = tid >> 5;
    float acc[4][4] = {};
    for (int k0 = 0; k0 < HH; k0 += 32) {
        #pragma unroll
        for (int j = 0; j < 4; j++) {
            int m = grp + j * 8;
            int r = r0 + m;
            int bb = r >> 7, s = r & 127;
            Ash[lane][m] = hs[(size_t)s * (SB * HH) + bb * HH + k0 + lane];
        }
        #pragma unroll
        for (int j = 0; j < 16; j++) {
            int nn = grp + j * 8;
            Wsh[lane][nn] = W[(size_t)(n0 + nn) * HH + k0 + lane];
        }
        __syncthreads();
        #pragma unroll
        for (int k = 0; k < 32; k++) {
            float4 a4 = *(const float4*)&Ash[k][grp * 4];
            float4 w4 = *(const float4*)&Wsh[k][lane * 4];
            acc[0][0] += a4.x * w4.x; acc[0][1] += a4.x * w4.y; acc[0][2] += a4.x * w4.z; acc[0][3] += a4.x * w4.w;
            acc[1][0] += a4.y * w4.x; acc[1][1] += a4.y * w4.y; acc[1][2] += a4.y * w4.z; acc[1][3] += a4.y * w4.w;
            acc[2][0] += a4.z * w4.x; acc[2][1] += a4.z * w4.y; acc[2][2] += a4.z * w4.z; acc[2][3] += a4.z * w4.w;
            acc[3][0] += a4.w * w4.x; acc[3][1] += a4.w * w4.y; acc[3][2] += a4.w * w4.z; acc[3][3] += a4.w * w4.w;
        }
        __syncthreads();
    }
    const int nbase = n0 + lane * 4;
    float4 b4 = *(const float4*)&bias[nbase];
    #pragma unroll
    for (int i = 0; i < 4; i++) {
        int r = r0 + grp * 4 + i;
        float4 v;
        v.x = acc[i][0] + b4.x; v.y = acc[i][1] + b4.y;
        v.z = acc[i][2] + b4.z; v.w = acc[i][3] + b4.w;
        *(float4*)&dst[(size_t)r * HH + nbase] = v;
    }
}

// ---------------- LSTM GEMM: grid(64 ntiles, 4 ksplits) x 256 thr ----------------
__global__ void lstm_gemm(int layer, int pin, int first, const float* __restrict__ emb,
                          const float* __restrict__ W_ih, const float* __restrict__ W_hh) {
    __shared__ float Ash[32][34];
    __shared__ float Wsh[32][34];
    __shared__ int tok_s[SB];
    const int tid = threadIdx.x;
    const int ks = blockIdx.y;             // 0..3
    const int np0 = blockIdx.x * 8;
    const int pout = pin ^ 1;
    const int lane = tid & 31, w = tid >> 5;
    const int tb = tid & 15, tn = tid >> 4;

    if (tid < SB)
        tok_s[tid] = first ? 0 : (int)(~(unsigned)(g_packed[tid] & 0xFFFFFFFFull));
    __syncthreads();

    const float* W = ((ks < 2) ? W_ih : W_hh) + (size_t)layer * 4 * HH * HH;
    const int kbase = (ks & 1) * 256;
    const bool emb_path = (ks < 2 && layer == 0);
    const float* xsrc = (ks < 2) ? &g_h[pout][0][0][0] : &g_h[pin][layer][0][0];

    float ra[4], rw[4];
    {
        const int k0 = kbase;
        if (emb_path) {
            #pragma unroll
            for (int i = 0; i < 4; i++)
                ra[i] = emb[(size_t)tok_s[w * 4 + i] * HH + k0 + lane];
        } else {
            #pragma unroll
            for (int j = 0; j < 4; j++) {
                int e = tid + j * 256;
                ra[j] = xsrc[(size_t)(k0 + (e >> 5)) * SB + (e & 31)];
            }
        }
        #pragma unroll
        for (int j = 0; j < 4; j++) {
            int e = tid + j * 256;
            int nl = e >> 5, kk = e & 31;
            int g = nl >> 3, np = np0 + (nl & 7);
            rw[j] = W[(size_t)(g * HH + np) * HH + k0 + kk];
        }
    }

    float acc[2][2] = {};
    for (int c = 0; c < 8; c++) {
        if (emb_path) {
            #pragma unroll
            for (int i = 0; i < 4; i++) Ash[lane][w * 4 + i] = ra[i];
        } else {
            #pragma unroll
            for (int j = 0; j < 4; j++) {
                int e = tid + j * 256;
                Ash[e >> 5][e & 31] = ra[j];
            }
        }
        #pragma unroll
        for (int j = 0; j < 4; j++) {
            int e = tid + j * 256;
            Wsh[e & 31][e >> 5] = rw[j];
        }
        __syncthreads();
        if (c < 7) {
            const int k0 = kbase + (c + 1) * 32;
            if (emb_path) {
                #pragma unroll
                for (int i = 0; i < 4; i++)
                    ra[i] = emb[(size_t)tok_s[w * 4 + i] * HH + k0 + lane];
            } else {
                #pragma unroll
                for (int j = 0; j < 4; j++) {
                    int e = tid + j * 256;
                    ra[j] = xsrc[(size_t)(k0 + (e >> 5)) * SB + (e & 31)];
                }
            }
            #pragma unroll
            for (int j = 0; j < 4; j++) {
                int e = tid + j * 256;
                int nl = e >> 5, kk = e & 31;
                int g = nl >> 3, np = np0 + (nl & 7);
                rw[j] = W[(size_t)(g * HH + np) * HH + k0 + kk];
            }
        }
        #pragma unroll
        for (int k = 0; k < 32; k++) {
            float2 a2 = *(const float2*)&Ash[k][tb * 2];
            float2 w2 = *(const float2*)&Wsh[k][tn * 2];
            acc[0][0] += a2.x * w2.x; acc[0][1] += a2.x * w2.y;
            acc[1][0] += a2.y * w2.x; acc[1][1] += a2.y * w2.y;
        }
        __syncthreads();
    }
    #pragma unroll
    for (int j = 0; j < 2; j++) {
        int nl = tn * 2 + j;
        int g = nl >> 3, np = np0 + (nl & 7);
        #pragma unroll
        for (int i = 0; i < 2; i++)
            g_gpart[ks][g][np][tb * 2 + i] = acc[i][j];
    }
}

// ---------------- LSTM activation ----------------
__global__ void lstm_act(int layer, int pin,
                         const float* __restrict__ b_ih, const float* __restrict__ b_hh) {
    const int idx = blockIdx.x * blockDim.x + threadIdx.x;   // 16384
    const int b = idx & 31, np = idx >> 5;
    const int pout = pin ^ 1;
    const float* bi = b_ih + (size_t)layer * 4 * HH;
    const float* bh = b_hh + (size_t)layer * 4 * HH;
    float s[4];
    #pragma unroll
    for (int g = 0; g < 4; g++)
        s[g] = (g_gpart[0][g][np][b] + g_gpart[1][g][np][b])
             + (g_gpart[2][g][np][b] + g_gpart[3][g][np][b])
             + bi[g * HH + np] + bh[g * HH + np];
    float cold = g_c[pin][layer][np][b];
    float cn = sigf(s[1]) * cold + sigf(s[0]) * tanhf(s[2]);
    float hn = sigf(s[3]) * tanhf(cn);
    g_c[pout][layer][np][b] = cn;
    g_h[pout][layer][np][b] = hn;
}

// ---------------- fused attention + Wo ----------------
__global__ void attnwo_kernel(int pout,
                              const float* __restrict__ Wq, const float* __restrict__ bq,
                              const float* __restrict__ Wo, const float* __restrict__ bo) {
    const int b = blockIdx.x;
    __shared__ float sx[HH];
    __shared__ float qs[HH];
    __shared__ float sc[8][SS];
    __shared__ float ax[HH];
    __shared__ float tot[8];
    const int tid = threadIdx.x;               // 512
    const int lane = tid & 31, w = tid >> 5;
    sx[tid] = g_h[pout][1][tid][b];
    __syncthreads();
    for (int jj = 0; jj < 32; jj++) {
        int j = w * 32 + jj;
        const float* wr = Wq + (size_t)j * HH;
        float s = 0.f;
        #pragma unroll 4
        for (int k = lane; k < HH; k += 32) s += sx[k] * wr[k];
        #pragma unroll
        for (int off = 16; off; off >>= 1) s += __shfl_xor_sync(0xffffffffu, s, off);
        if (lane == 0) qs[j] = s + bq[j];
    }
    __syncthreads();
    #pragma unroll
    for (int i = 0; i < 2; i++) {
        int idx = tid + i * 512;
        int hd = idx >> 7, s = idx & 127;
        const float* kr = &g_k[b][s][hd * 64];
        const float* qr = &qs[hd * 64];
        float acc = 0.f;
        #pragma unroll 16
        for (int d = 0; d < 64; d++) acc += qr[d] * kr[d];
        sc[hd][s] = acc * 0.125f;
    }
    __syncthreads();
    if (w < 8) {
        float v0 = sc[w][lane], v1 = sc[w][lane + 32];
        float v2 = sc[w][lane + 64], v3 = sc[w][lane + 96];
        float m = fmaxf(fmaxf(v0, v1), fmaxf(v2, v3));
        #pragma unroll
        for (int off = 16; off; off >>= 1) m = fmaxf(m, __shfl_xor_sync(0xffffffffu, m, off));
        float e0 = expf(v0 - m), e1 = expf(v1 - m), e2 = expf(v2 - m), e3 = expf(v3 - m);
        float s = (e0 + e1) + (e2 + e3);
        #pragma unroll
        for (int off = 16; off; off >>= 1) s += __shfl_xor_sync(0xffffffffu, s, off);
        sc[w][lane] = e0; sc[w][lane + 32] = e1; sc[w][lane + 64] = e2; sc[w][lane + 96] = e3;
        if (lane == 0) tot[w] = s;
    }
    __syncthreads();
    {
        int hd = tid >> 6;
        float acc = 0.f;
        #pragma unroll 8
        for (int s = 0; s < SS; s++) acc += sc[hd][s] * g_v[b][s][tid];
        ax[tid] = acc / tot[hd];
    }
    __syncthreads();
    for (int jj = 0; jj < 32; jj++) {
        int j = w * 32 + jj;
        const float* wr = Wo + (size_t)j * HH;
        float s = 0.f;
        #pragma unroll 4
        for (int k = lane; k < HH; k += 32) s += ax[k] * wr[k];
        #pragma unroll
        for (int off = 16; off; off >>= 1) s += __shfl_xor_sync(0xffffffffu, s, off);
        if (lane == 0) g_attno[b][j] = s + bo[j];
    }
}

// ---------------- logits via mma.sync bf16-split: 250 CTAs x 128 cols ----------------
__global__ void __launch_bounds__(256, 2)
logits_mma(const float* __restrict__ bout, float* __restrict__ out, int t) {
    extern __shared__ char smem[];
    __nv_bfloat16* As = (__nv_bfloat16*)smem;              // [2*32][ASTRIDE]
    __nv_bfloat16* Bs = (__nv_bfloat16*)(smem + BOFF);     // [2*128][BSTRIDE]
    const int tid = threadIdx.x, lane = tid & 31, w = tid >> 5;
    const int n0 = blockIdx.x * 128;
    const int nw = w * 16;
    const uint32_t as_u32 = smem_u32(As);
    const uint32_t bs_u32 = smem_u32(Bs);

    // A fill: rows 0-31 = bf16_hi(attno), rows 32-63 = bf16_lo
    for (int i = tid; i < 32 * 512; i += 256) {
        int m = i >> 9, k = i & 511;
        float x = g_attno[m][k];
        __nv_bfloat16 hb = __float2bfloat16(x);
        As[m * ASTRIDE + k] = hb;
        As[(32 + m) * ASTRIDE + k] = __float2bfloat16(x - __bfloat162float(hb));
    }

    // prefetch B chunk 0 (both splits) into registers
    uint4 pre[8];
    #pragma unroll
    for (int j = 0; j < 8; j++) {
        int e = j * 256 + tid;
        int s = e >> 10, idx = e & 1023;
        int row = idx >> 3, q = idx & 7;
        const __nv_bfloat16* src = s ? g_wl : g_wh;
        pre[j] = *(const uint4*)(src + (size_t)(n0 + row) * HH + q * 8);
    }

    float acc[2][2][4] = {};
    for (int kc = 0; kc < 8; kc++) {
        // commit staged regs to smem
        #pragma unroll
        for (int j = 0; j < 8; j++) {
            int e = j * 256 + tid;
            int s = e >> 10, idx = e & 1023;
            int row = idx >> 3, q = idx & 7;
            *(uint4*)&Bs[(s * 128 + row) * BSTRIDE + q * 8] = pre[j];
        }
        __syncthreads();
        // prefetch next chunk
        if (kc < 7) {
            #pragma unroll
            for (int j = 0; j < 8; j++) {
                int e = j * 256 + tid;
                int s = e >> 10, idx = e & 1023;
                int row = idx >> 3, q = idx & 7;
                const __nv_bfloat16* src = s ? g_wl : g_wh;
                pre[j] = *(const uint4*)(src + (size_t)(n0 + row) * HH + (kc + 1) * 64 + q * 8);
            }
        }
        // compute: 4 k16 steps over this chunk
        #pragma unroll
        for (int kk = 0; kk < 64; kk += 16) {
            const int ka = kc * 64 + kk;
            uint32_t ah[2][4], al[2][4], bh[2][2], bl[2][2];
            #pragma unroll
            for (int mt = 0; mt < 2; mt++) {
                int r = mt * 16 + (lane & 15);
                int k = ka + (((lane >> 4) & 1) << 3);
                ldsm_x4(ah[mt], as_u32 + (r * ASTRIDE + k) * 2);
                ldsm_x4(al[mt], as_u32 + ((32 + r) * ASTRIDE + k) * 2);
            }
            #pragma unroll
            for (int nt = 0; nt < 2; nt++) {
                int nrow = nw + nt * 8 + (lane & 7);
                int k = kk + ((lane & 8) ? 8 : 0);
                ldsm_x2(bh[nt], bs_u32 + (nrow * BSTRIDE + k) * 2);
                ldsm_x2(bl[nt], bs_u32 + ((128 + nrow) * BSTRIDE + k) * 2);
            }
            #pragma unroll
            for (int mt = 0; mt < 2; mt++)
                #pragma unroll
                for (int nt = 0; nt < 2; nt++) {
                    mma_bf16(acc[mt][nt], ah[mt], bh[nt]);
                    mma_bf16(acc[mt][nt], ah[mt], bl[nt]);
                    mma_bf16(acc[mt][nt], al[mt], bh[nt]);
                }
        }
        __syncthreads();
    }

    // epilogue: + bias, store
    #pragma unroll
    for (int mt = 0; mt < 2; mt++)
        #pragma unroll
        for (int nt = 0; nt < 2; nt++) {
            int n = n0 + nw + nt * 8 + (lane & 3) * 2;
            float2 bias = *(const float2*)&bout[n];
            #pragma unroll
            for (int h = 0; h < 2; h++) {
                int b = mt * 16 + (lane >> 2) + h * 8;
                float2 v;
                v.x = acc[mt][nt][h * 2] + bias.x;
                v.y = acc[mt][nt][h * 2 + 1] + bias.y;
                *(float2*)&out[((size_t)b * SS + t + 1) * VV + n] = v;
            }
        }
}

// ---------------- argmax: scan stored logits for max, fp32-recompute candidates ----------------
__global__ void argmax_fix(const float* __restrict__ Wout, const float* __restrict__ bout,
                           const float* __restrict__ out, int t) {
    const int b = blockIdx.x;
    __shared__ float sredf[8];
    __shared__ unsigned long long sred[8];
    const int lane = threadIdx.x & 31, w = threadIdx.x >> 5;
    const float* row = out + ((size_t)b * SS + t + 1) * VV;
    // pass 1: approx max over stored row
    float m = -1e30f;
    for (int n4 = threadIdx.x; n4 < VV / 4; n4 += blockDim.x) {
        float4 v = *(const float4*)&row[n4 * 4];
        m = fmaxf(m, fmaxf(fmaxf(v.x, v.y), fmaxf(v.z, v.w)));
    }
    #pragma unroll
    for (int off = 16; off; off >>= 1) m = fmaxf(m, __shfl_xor_sync(0xffffffffu, m, off));
    if (lane == 0) sredf[w] = m;
    __syncthreads();
    float rowmax = sredf[0];
    #pragma unroll
    for (int i = 1; i < 8; i++) rowmax = fmaxf(rowmax, sredf[i]);
    const float thr = rowmax - 1e-2f;
    // pass 2: exact fp32 dot for candidates
    unsigned long long best = 0ull;
    for (int n4 = threadIdx.x; n4 < VV / 4; n4 += blockDim.x) {
        float4 v = *(const float4*)&row[n4 * 4];
        float mv = fmaxf(fmaxf(v.x, v.y), fmaxf(v.z, v.w));
        if (mv >= thr) {
            float vv[4] = {v.x, v.y, v.z, v.w};
            #pragma unroll
            for (int j = 0; j < 4; j++) {
                if (vv[j] >= thr) {
                    int n = n4 * 4 + j;
                    const float* wr = Wout + (size_t)n * HH;
                    float d = 0.f;
                    for (int k = 0; k < HH; k++) d += g_attno[b][k] * wr[k];
                    d += bout[n];
                    unsigned long long key = amax_key(d, n);
                    if (key > best) best = key;
                }
            }
        }
    }
    #pragma unroll
    for (int off = 16; off; off >>= 1) {
        unsigned long long o = __shfl_xor_sync(0xffffffffu, best, off);
        if (o > best) best = o;
    }
    if (lane == 0) sred[w] = best;
    __syncthreads();
    if (threadIdx.x == 0) {
        unsigned long long mm = sred[0];
        #pragma unroll
        for (int i = 1; i < 8; i++) if (sred[i] > mm) mm = sred[i];
        g_packed[b] = mm;
    }
}

// ---------------- launch sequence ----------------
extern "C" void kernel_launch(void* const* d_in, const int* in_sizes, int n_in,
                              void* d_out, int out_size) {
    const float* hs     = (const float*)d_in[0];
    const float* hidden = (const float*)d_in[1];
    const float* cell   = (const float*)d_in[2];
    const float* emb    = (const float*)d_in[3];
    const float* W_ih   = (const float*)d_in[4];
    const float* W_hh   = (const float*)d_in[5];
    const float* b_ih   = (const float*)d_in[6];
    const float* b_hh   = (const float*)d_in[7];
    const float* Wq     = (const float*)d_in[8];
    const float* bq     = (const float*)d_in[9];
    const float* Wk     = (const float*)d_in[10];
    const float* bk     = (const float*)d_in[11];
    const float* Wv     = (const float*)d_in[12];
    const float* bv     = (const float*)d_in[13];
    const float* Wo     = (const float*)d_in[14];
    const float* bo     = (const float*)d_in[15];
    const float* W_out  = (const float*)d_in[16];
    const float* b_out  = (const float*)d_in[17];
    float* out = (float*)d_out;

    cudaFuncSetAttribute(logits_mma, cudaFuncAttributeMaxDynamicSharedMemorySize, L_SMEM_TOTAL);

    init_kernel<<<4000, 256>>>(hidden, cell, W_out, out);

    dim3 kvg(128, 4);
    kv_kernel<<<kvg, 256>>>(hs, Wk, bk, 0);
    kv_kernel<<<kvg, 256>>>(hs, Wv, bv, 1);

    dim3 lg(64, 4);
    for (int t = 0; t < NSTEP; t++) {
        int pin = t & 1;
        lstm_gemm<<<lg, 256>>>(0, pin, (t == 0) ? 1 : 0, emb, W_ih, W_hh);
        lstm_act<<<64, 256>>>(0, pin, b_ih, b_hh);
        lstm_gemm<<<lg, 256>>>(1, pin, 0, emb, W_ih, W_hh);
        lstm_act<<<64, 256>>>(1, pin, b_ih, b_hh);
        attnwo_kernel<<<SB, 512>>>(pin ^ 1, Wq, bq, Wo, bo);
        logits_mma<<<250, 256, L_SMEM_TOTAL>>>(b_out, out, t);
        argmax_fix<<<SB, 256>>>(W_out, b_out, out, t);
    }
}

// round 6
// speedup vs baseline: 1.9760x; 1.4020x over previous
#include <cuda_runtime.h>
#include <cuda_bf16.h>
#include <cstdint>

#define SB 32      // batch
#define SS 128     // source length / max_len
#define HH 512     // hidden
#define VV 32000   // vocab
#define NSTEP 127  // decode steps
#define NCTA 148   // persistent grid (1 CTA/SM)

// ---------------- persistent device state ----------------
__device__ float g_h[2][2][HH][SB];          // [pingpong][layer][dim][b]
__device__ float g_c[2][2][HH][SB];
__device__ float g_k[SB][SS][HH];
__device__ float g_v[SB][SS][HH];
__device__ float g_attnT[HH][SB];            // attention (pre-Wo), transposed
__device__ float g_attno[SB][HH];            // after Wo
__device__ unsigned long long g_packed[SB];
__device__ __nv_bfloat16 g_wh[(size_t)VV * HH];
__device__ __nv_bfloat16 g_wl[(size_t)VV * HH];
__device__ unsigned g_cnt = 0;
__device__ unsigned g_gen = 0;

__device__ __forceinline__ float sigf(float x) { return 1.f / (1.f + expf(-x)); }

__device__ __forceinline__ unsigned long long amax_key(float v, int n) {
    unsigned u = __float_as_uint(v);
    u = (u & 0x80000000u) ? ~u : (u | 0x80000000u);
    return ((unsigned long long)u << 32) | (unsigned)(~(unsigned)n);
}

// ---------------- grid barrier (persistent kernel) ----------------
__device__ __forceinline__ void gridbar() {
    __syncthreads();
    if (threadIdx.x == 0) {
        __threadfence();
        unsigned gen = atomicAdd(&g_gen, 0u);
        if (atomicAdd(&g_cnt, 1u) == (unsigned)(gridDim.x - 1)) {
            atomicExch(&g_cnt, 0u);
            atomicAdd(&g_gen, 1u);
        } else {
            while (atomicAdd(&g_gen, 0u) == gen) __nanosleep(100);
        }
    }
    __syncthreads();
}

// ---------------- mma helpers ----------------
__device__ __forceinline__ uint32_t smem_u32(const void* p) {
    uint32_t a;
    asm("{ .reg .u64 t; cvta.to.shared.u64 t, %1; cvt.u32.u64 %0, t; }" : "=r"(a) : "l"(p));
    return a;
}
__device__ __forceinline__ void ldsm_x4(uint32_t* r, uint32_t addr) {
    asm volatile("ldmatrix.sync.aligned.m8n8.x4.shared.b16 {%0,%1,%2,%3}, [%4];"
                 : "=r"(r[0]), "=r"(r[1]), "=r"(r[2]), "=r"(r[3]) : "r"(addr));
}
__device__ __forceinline__ void ldsm_x2(uint32_t* r, uint32_t addr) {
    asm volatile("ldmatrix.sync.aligned.m8n8.x2.shared.b16 {%0,%1}, [%2];"
                 : "=r"(r[0]), "=r"(r[1]) : "r"(addr));
}
__device__ __forceinline__ void mma_bf16(float* c, const uint32_t* a, const uint32_t* b) {
    asm volatile(
        "mma.sync.aligned.m16n8k16.row.col.f32.bf16.bf16.f32 "
        "{%0,%1,%2,%3}, {%4,%5,%6,%7}, {%8,%9}, {%0,%1,%2,%3};"
        : "+f"(c[0]), "+f"(c[1]), "+f"(c[2]), "+f"(c[3])
        : "r"(a[0]), "r"(a[1]), "r"(a[2]), "r"(a[3]), "r"(b[0]), "r"(b[1]));
}

#define ASTRIDE 520
#define BSTRIDE 40
#define L_ABYTES (64 * ASTRIDE * 2)           // 66560
#define L_BBYTES (512 * BSTRIDE * 2)          // 40960
#define SMEM_DYN (L_ABYTES + L_BBYTES)        // 107520

// ---------------- init (once per replay) ----------------
__global__ void init_kernel(const float* __restrict__ hidden,
                            const float* __restrict__ cell,
                            const float* __restrict__ W_out,
                            float* __restrict__ out) {
    int idx = blockIdx.x * blockDim.x + threadIdx.x;
    const int nhc = 2 * SB * HH;
    if (idx < nhc) {
        int l = idx >> 14, b = (idx >> 9) & 31, h = idx & 511;
        g_h[0][l][h][b] = hidden[idx];
        g_c[0][l][h][b] = cell[idx];
    }
    if (idx < SB * VV) {
        int b = idx / VV, v = idx % VV;
        out[(size_t)b * SS * VV + v] = 0.f;
    }
    const size_t nw = (size_t)VV * HH;
    const size_t stride = (size_t)gridDim.x * blockDim.x;
    for (size_t i = idx; i < nw; i += stride) {
        float w = W_out[i];
        __nv_bfloat16 h = __float2bfloat16(w);
        g_wh[i] = h;
        g_wl[i] = __float2bfloat16(w - __bfloat162float(h));
    }
}

// ---------------- K/V projection (once per replay) ----------------
__global__ void kv_kernel(const float* __restrict__ hs, const float* __restrict__ W,
                          const float* __restrict__ bias, int which) {
    __shared__ float Ash[32][36];
    __shared__ float Wsh[32][132];
    float* dst = which ? &g_v[0][0][0] : &g_k[0][0][0];
    const int r0 = blockIdx.x * 32;
    const int n0 = blockIdx.y * 128;
    const int tid = threadIdx.x;
    const int lane = tid & 31, grp = tid >> 5;
    float acc[4][4] = {};
    for (int k0 = 0; k0 < HH; k0 += 32) {
        #pragma unroll
        for (int j = 0; j < 4; j++) {
            int m = grp + j * 8;
            int r = r0 + m;
            int bb = r >> 7, s = r & 127;
            Ash[lane][m] = hs[(size_t)s * (SB * HH) + bb * HH + k0 + lane];
        }
        #pragma unroll
        for (int j = 0; j < 16; j++) {
            int nn = grp + j * 8;
            Wsh[lane][nn] = W[(size_t)(n0 + nn) * HH + k0 + lane];
        }
        __syncthreads();
        #pragma unroll
        for (int k = 0; k < 32; k++) {
            float4 a4 = *(const float4*)&Ash[k][grp * 4];
            float4 w4 = *(const float4*)&Wsh[k][lane * 4];
            acc[0][0] += a4.x * w4.x; acc[0][1] += a4.x * w4.y; acc[0][2] += a4.x * w4.z; acc[0][3] += a4.x * w4.w;
            acc[1][0] += a4.y * w4.x; acc[1][1] += a4.y * w4.y; acc[1][2] += a4.y * w4.z; acc[1][3] += a4.y * w4.w;
            acc[2][0] += a4.z * w4.x; acc[2][1] += a4.z * w4.y; acc[2][2] += a4.z * w4.z; acc[2][3] += a4.z * w4.w;
            acc[3][0] += a4.w * w4.x; acc[3][1] += a4.w * w4.y; acc[3][2] += a4.w * w4.z; acc[3][3] += a4.w * w4.w;
        }
        __syncthreads();
    }
    const int nbase = n0 + lane * 4;
    float4 b4 = *(const float4*)&bias[nbase];
    #pragma unroll
    for (int i = 0; i < 4; i++) {
        int r = r0 + grp * 4 + i;
        float4 v;
        v.x = acc[i][0] + b4.x; v.y = acc[i][1] + b4.y;
        v.z = acc[i][2] + b4.z; v.w = acc[i][3] + b4.w;
        *(float4*)&dst[(size_t)r * HH + nbase] = v;
    }
}

// =================== persistent decoder phases ===================

__device__ void lstm_phase(int layer, int pin, int first, char* smem,
                           const float* __restrict__ emb,
                           const float* __restrict__ W_ih, const float* __restrict__ W_hh,
                           const float* __restrict__ b_ih, const float* __restrict__ b_hh) {
    float (*As)[34] = (float(*)[34])smem;                       // [32][34]
    float (*Ws)[17] = (float(*)[17])(smem + 32 * 34 * 4);       // [32][17]
    float (*Acc)[34] = (float(*)[34])(smem + 32 * 34 * 4 + 32 * 17 * 4);   // [16][34]
    int* tok_s = (int*)(smem + 32 * 34 * 4 + 32 * 17 * 4 + 16 * 34 * 4);
    const int tid = threadIdx.x;
    const int lane = tid & 31, w = tid >> 5;
    const int pout = pin ^ 1;
    const float* Wi = W_ih + (size_t)layer * 4 * HH * HH;
    const float* Whh = W_hh + (size_t)layer * 4 * HH * HH;

    for (int tile = blockIdx.x; tile < 128; tile += gridDim.x) {
        const int np0 = tile * 4;
        if (layer == 0 && tid < SB) {
            unsigned long long pk = __ldcg(&g_packed[tid]);
            tok_s[tid] = first ? 0 : (int)(~(unsigned)(pk & 0xFFFFFFFFull));
        }
        __syncthreads();

        float ra[4], rw[2];
        // chunk loaders
        auto loadA = [&](int c, float* r) {
            int kg = c * 32;
            if (layer == 0 && kg < HH) {
                #pragma unroll
                for (int i = 0; i < 4; i++)
                    r[i] = emb[(size_t)tok_s[w * 4 + i] * HH + kg + lane];
            } else {
                const float* src;
                int koff;
                if (kg < HH) { src = &g_h[pout][0][0][0]; koff = kg; }
                else         { src = &g_h[pin][layer][0][0]; koff = kg - HH; }
                #pragma unroll
                for (int j = 0; j < 4; j++) {
                    int e = tid + j * 256;
                    r[j] = __ldcg(&src[(size_t)(koff + (e >> 5)) * SB + (e & 31)]);
                }
            }
        };
        auto loadW = [&](int c, float* r) {
            int kg = c * 32;
            const float* Wsrc = (kg < HH) ? Wi : Whh;
            int koff = (kg < HH) ? kg : kg - HH;
            #pragma unroll
            for (int j = 0; j < 2; j++) {
                int e = tid + j * 256;
                int rr = e >> 5, kk = e & 31;
                int g = rr >> 2, i = rr & 3;
                r[j] = Wsrc[(size_t)(g * HH + np0 + i) * HH + koff + kk];
            }
        };

        loadA(0, ra); loadW(0, rw);
        float2 acc = make_float2(0.f, 0.f);
        const int r_ = tid >> 4, bb = (tid & 15) * 2;
        for (int c = 0; c < 32; c++) {
            if (layer == 0 && c < 16) {
                #pragma unroll
                for (int i = 0; i < 4; i++) As[lane][w * 4 + i] = ra[i];
            } else {
                #pragma unroll
                for (int j = 0; j < 4; j++) {
                    int e = tid + j * 256;
                    As[e >> 5][e & 31] = ra[j];
                }
            }
            #pragma unroll
            for (int j = 0; j < 2; j++) {
                int e = tid + j * 256;
                Ws[e & 31][e >> 5] = rw[j];
            }
            __syncthreads();
            if (c < 31) { loadA(c + 1, ra); loadW(c + 1, rw); }
            #pragma unroll
            for (int k = 0; k < 32; k++) {
                float2 a2 = *(const float2*)&As[k][bb];
                float wv = Ws[k][r_];
                acc.x += a2.x * wv;
                acc.y += a2.y * wv;
            }
            __syncthreads();
        }
        Acc[r_][bb] = acc.x;
        Acc[r_][bb + 1] = acc.y;
        __syncthreads();
        if (tid < 128) {
            int i = tid >> 5, b = tid & 31;
            const size_t bo_ = (size_t)layer * 4 * HH;
            float s[4];
            #pragma unroll
            for (int g = 0; g < 4; g++)
                s[g] = Acc[g * 4 + i][b] + b_ih[bo_ + g * HH + np0 + i] + b_hh[bo_ + g * HH + np0 + i];
            float cold = __ldcg(&g_c[pin][layer][np0 + i][b]);
            float cn = sigf(s[1]) * cold + sigf(s[0]) * tanhf(s[2]);
            float hn = sigf(s[3]) * tanhf(cn);
            __stcg(&g_c[pout][layer][np0 + i][b], cn);
            __stcg(&g_h[pout][layer][np0 + i][b], hn);
        }
        __syncthreads();
    }
}

__device__ void attn_phase(int pout, char* smem,
                           const float* __restrict__ Wq, const float* __restrict__ bq) {
    float* sxx = (float*)smem;                // 512
    float* qs = sxx + 512;                    // 64
    float* sc = qs + 64;                      // 128
    float* red = sc + 128;                    // 8
    float (*pav)[64] = (float(*)[64])(red + 8);
    const int tid = threadIdx.x;
    const int lane = tid & 31, w = tid >> 5;

    for (int u = blockIdx.x; u < 256; u += gridDim.x) {
        const int b = u >> 3, hd = u & 7;
        for (int d = tid; d < HH; d += 256) sxx[d] = __ldcg(&g_h[pout][1][d][b]);
        __syncthreads();
        #pragma unroll 1
        for (int jj = 0; jj < 8; jj++) {
            int j = hd * 64 + w * 8 + jj;
            const float* wr = Wq + (size_t)j * HH;
            float s = 0.f;
            #pragma unroll 4
            for (int k = lane; k < HH; k += 32) s += sxx[k] * wr[k];
            #pragma unroll
            for (int off = 16; off; off >>= 1) s += __shfl_xor_sync(0xffffffffu, s, off);
            if (lane == 0) qs[w * 8 + jj] = s + bq[j];
        }
        __syncthreads();
        if (tid < 128) {
            const float4* kr = (const float4*)&g_k[b][tid][hd * 64];
            const float4* q4 = (const float4*)qs;
            float acc = 0.f;
            #pragma unroll
            for (int d4 = 0; d4 < 16; d4++) {
                float4 kv = kr[d4], qv = q4[d4];
                acc += qv.x * kv.x + qv.y * kv.y + qv.z * kv.z + qv.w * kv.w;
            }
            sc[tid] = acc * 0.125f;
        }
        __syncthreads();
        if (tid < 32) {
            float m = fmaxf(fmaxf(sc[tid], sc[tid + 32]), fmaxf(sc[tid + 64], sc[tid + 96]));
            #pragma unroll
            for (int off = 16; off; off >>= 1) m = fmaxf(m, __shfl_xor_sync(0xffffffffu, m, off));
            if (lane == 0) red[0] = m;
        }
        __syncthreads();
        float mm = red[0];
        if (tid < 128) {
            float e = expf(sc[tid] - mm);
            sc[tid] = e;
            float s = e;
            #pragma unroll
            for (int off = 16; off; off >>= 1) s += __shfl_xor_sync(0xffffffffu, s, off);
            if (lane == 0) red[1 + w] = s;
        }
        __syncthreads();
        float tot = red[1] + red[2] + red[3] + red[4];
        {
            int d = tid & 63, sg = tid >> 6;
            float acc = 0.f;
            #pragma unroll 8
            for (int s5 = 0; s5 < 32; s5++) {
                int s = sg * 32 + s5;
                acc += sc[s] * g_v[b][s][hd * 64 + d];
            }
            pav[sg][d] = acc;
        }
        __syncthreads();
        if (tid < 64)
            __stcg(&g_attnT[hd * 64 + tid][b],
                   (pav[0][tid] + pav[1][tid] + pav[2][tid] + pav[3][tid]) / tot);
        __syncthreads();
    }
}

__device__ void wo_phase(char* smem, const float* __restrict__ Wo, const float* __restrict__ bo) {
    float (*xs)[34] = (float(*)[34])smem;                  // [32][34]
    float (*ws)[4] = (float(*)[4])(smem + 32 * 34 * 4);    // [32][4]
    const int tid = threadIdx.x;
    for (int tile = blockIdx.x; tile < 128; tile += gridDim.x) {
        const int d0 = tile * 4;
        float acc = 0.f;
        const int r_ = tid >> 5, b = tid & 31;
        for (int kc = 0; kc < 16; kc++) {
            #pragma unroll
            for (int j = 0; j < 4; j++) {
                int e = tid + j * 256;
                xs[e >> 5][e & 31] = __ldcg(&g_attnT[kc * 32 + (e >> 5)][e & 31]);
            }
            if (tid < 128)
                ws[tid & 31][tid >> 5] = Wo[(size_t)(d0 + (tid >> 5)) * HH + kc * 32 + (tid & 31)];
            __syncthreads();
            if (tid < 128) {
                #pragma unroll
                for (int k = 0; k < 32; k++) acc += xs[k][b] * ws[k][r_];
            }
            __syncthreads();
        }
        if (tid < 128) __stcg(&g_attno[b][d0 + r_], acc + bo[d0 + r_]);
        __syncthreads();
    }
}

__device__ void logits_phase(char* smem, const float* __restrict__ bout,
                             float* __restrict__ out, int t) {
    __nv_bfloat16* As = (__nv_bfloat16*)smem;
    __nv_bfloat16* Bs = (__nv_bfloat16*)(smem + L_ABYTES);
    const int tid = threadIdx.x, lane = tid & 31, w = tid >> 5;
    const uint32_t as_u = smem_u32(As);
    const uint32_t bs_u = smem_u32(Bs);

    for (int tile = blockIdx.x; tile < 125; tile += gridDim.x) {
        const int n0 = tile * 256;
        // A fill (both splits)
        for (int i2 = tid; i2 < 32 * HH; i2 += 256) {
            int m = i2 >> 9, k = i2 & 511;
            float x = __ldcg(&g_attno[m][k]);
            __nv_bfloat16 hb = __float2bfloat16(x);
            As[m * ASTRIDE + k] = hb;
            As[(32 + m) * ASTRIDE + k] = __float2bfloat16(x - __bfloat162float(hb));
        }
        __syncthreads();

        uint4 pre[8];
        auto loadB = [&](int c, uint4* r) {
            #pragma unroll
            for (int j = 0; j < 8; j++) {
                int e = j * 256 + tid;
                int rr = e >> 2, q = e & 3;
                const __nv_bfloat16* src = (rr & 256) ? g_wl : g_wh;
                int nr = rr & 255;
                r[j] = *(const uint4*)(src + (size_t)(n0 + nr) * HH + c * 32 + q * 8);
            }
        };
        loadB(0, pre);
        float acc[2][4][4] = {};
        for (int kc = 0; kc < 16; kc++) {
            #pragma unroll
            for (int j = 0; j < 8; j++) {
                int e = j * 256 + tid;
                int rr = e >> 2, q = e & 3;
                *(uint4*)&Bs[rr * BSTRIDE + q * 8] = pre[j];
            }
            __syncthreads();
            if (kc < 15) loadB(kc + 1, pre);
            #pragma unroll
            for (int kk = 0; kk < 32; kk += 16) {
                const int ka = kc * 32 + kk;
                uint32_t ah[2][4], al[2][4], bh[4][2], bl[4][2];
                #pragma unroll
                for (int mt = 0; mt < 2; mt++) {
                    int r = mt * 16 + (lane & 15);
                    int k = ka + (((lane >> 4) & 1) << 3);
                    ldsm_x4(ah[mt], as_u + (r * ASTRIDE + k) * 2);
                    ldsm_x4(al[mt], as_u + ((32 + r) * ASTRIDE + k) * 2);
                }
                #pragma unroll
                for (int nt = 0; nt < 4; nt++) {
                    int nrow = w * 32 + nt * 8 + (lane & 7);
                    int k = kk + ((lane & 8) ? 8 : 0);
                    ldsm_x2(bh[nt], bs_u + (nrow * BSTRIDE + k) * 2);
                    ldsm_x2(bl[nt], bs_u + ((256 + nrow) * BSTRIDE + k) * 2);
                }
                #pragma unroll
                for (int mt = 0; mt < 2; mt++)
                    #pragma unroll
                    for (int nt = 0; nt < 4; nt++) {
                        mma_bf16(acc[mt][nt], ah[mt], bh[nt]);
                        mma_bf16(acc[mt][nt], ah[mt], bl[nt]);
                        mma_bf16(acc[mt][nt], al[mt], bh[nt]);
                    }
            }
            __syncthreads();
        }
        #pragma unroll
        for (int mt = 0; mt < 2; mt++)
            #pragma unroll
            for (int nt = 0; nt < 4; nt++) {
                int n = n0 + w * 32 + nt * 8 + (lane & 3) * 2;
                float2 bias = *(const float2*)&bout[n];
                #pragma unroll
                for (int h = 0; h < 2; h++) {
                    int b = mt * 16 + (lane >> 2) + h * 8;
                    float2 v;
                    v.x = acc[mt][nt][h * 2] + bias.x;
                    v.y = acc[mt][nt][h * 2 + 1] + bias.y;
                    *(float2*)&out[((size_t)b * SS + t + 1) * VV + n] = v;
                }
            }
        __syncthreads();
    }
}

__device__ void fix_phase(char* smem, const float* __restrict__ Wout,
                          const float* __restrict__ bout,
                          const float* __restrict__ out, int t) {
    float* ax = (float*)smem;                 // 512
    float* redf = ax + 512;                   // 8
    unsigned long long* redk = (unsigned long long*)(redf + 8);
    const int tid = threadIdx.x;
    const int lane = tid & 31, w = tid >> 5;
    for (int b = blockIdx.x; b < SB; b += gridDim.x) {
        for (int d = tid; d < HH; d += 256) ax[d] = __ldcg(&g_attno[b][d]);
        const float* row = out + ((size_t)b * SS + t + 1) * VV;
        float m = -1e30f;
        for (int n4 = tid; n4 < VV / 4; n4 += 256) {
            float4 v = __ldcg((const float4*)&row[n4 * 4]);
            m = fmaxf(m, fmaxf(fmaxf(v.x, v.y), fmaxf(v.z, v.w)));
        }
        #pragma unroll
        for (int off = 16; off; off >>= 1) m = fmaxf(m, __shfl_xor_sync(0xffffffffu, m, off));
        if (lane == 0) redf[w] = m;
        __syncthreads();
        float rowmax = redf[0];
        #pragma unroll
        for (int i = 1; i < 8; i++) rowmax = fmaxf(rowmax, redf[i]);
        const float thr = rowmax - 1e-2f;
        unsigned long long best = 0ull;
        for (int n4 = tid; n4 < VV / 4; n4 += 256) {
            float4 v = __ldcg((const float4*)&row[n4 * 4]);
            float mv = fmaxf(fmaxf(v.x, v.y), fmaxf(v.z, v.w));
            if (mv >= thr) {
                float vv[4] = {v.x, v.y, v.z, v.w};
                #pragma unroll
                for (int j = 0; j < 4; j++) {
                    if (vv[j] >= thr) {
                        int n = n4 * 4 + j;
                        const float* wr = Wout + (size_t)n * HH;
                        float d = 0.f;
                        for (int k = 0; k < HH; k++) d += ax[k] * wr[k];
                        d += bout[n];
                        unsigned long long key = amax_key(d, n);
                        if (key > best) best = key;
                    }
                }
            }
        }
        #pragma unroll
        for (int off = 16; off; off >>= 1) {
            unsigned long long o = __shfl_xor_sync(0xffffffffu, best, off);
            if (o > best) best = o;
        }
        if (lane == 0) redk[w] = best;
        __syncthreads();
        if (tid == 0) {
            unsigned long long mm = redk[0];
            #pragma unroll
            for (int i = 1; i < 8; i++) if (redk[i] > mm) mm = redk[i];
            __stcg(&g_packed[b], mm);
        }
        __syncthreads();
    }
}

// ---------------- the persistent kernel ----------------
__global__ void __launch_bounds__(256, 1)
decoder_persist(const float* __restrict__ emb,
                const float* __restrict__ W_ih, const float* __restrict__ W_hh,
                const float* __restrict__ b_ih, const float* __restrict__ b_hh,
                const float* __restrict__ Wq, const float* __restrict__ bq,
                const float* __restrict__ Wo, const float* __restrict__ bo,
                const float* __restrict__ W_out, const float* __restrict__ b_out,
                float* __restrict__ out) {
    extern __shared__ char smem[];
    for (int t = 0; t < NSTEP; t++) {
        const int pin = t & 1;
        lstm_phase(0, pin, t == 0, smem, emb, W_ih, W_hh, b_ih, b_hh);
        gridbar();
        lstm_phase(1, pin, 0, smem, emb, W_ih, W_hh, b_ih, b_hh);
        gridbar();
        attn_phase(pin ^ 1, smem, Wq, bq);
        gridbar();
        wo_phase(smem, Wo, bo);
        gridbar();
        logits_phase(smem, b_out, out, t);
        gridbar();
        fix_phase(smem, W_out, b_out, out, t);
        gridbar();
    }
}

// ---------------- launch sequence ----------------
extern "C" void kernel_launch(void* const* d_in, const int* in_sizes, int n_in,
                              void* d_out, int out_size) {
    const float* hs     = (const float*)d_in[0];
    const float* hidden = (const float*)d_in[1];
    const float* cell   = (const float*)d_in[2];
    const float* emb    = (const float*)d_in[3];
    const float* W_ih   = (const float*)d_in[4];
    const float* W_hh   = (const float*)d_in[5];
    const float* b_ih   = (const float*)d_in[6];
    const float* b_hh   = (const float*)d_in[7];
    const float* Wq     = (const float*)d_in[8];
    const float* bq     = (const float*)d_in[9];
    const float* Wk     = (const float*)d_in[10];
    const float* bk     = (const float*)d_in[11];
    const float* Wv     = (const float*)d_in[12];
    const float* bv     = (const float*)d_in[13];
    const float* Wo     = (const float*)d_in[14];
    const float* bo     = (const float*)d_in[15];
    const float* W_out  = (const float*)d_in[16];
    const float* b_out  = (const float*)d_in[17];
    float* out = (float*)d_out;

    cudaFuncSetAttribute(decoder_persist, cudaFuncAttributeMaxDynamicSharedMemorySize, SMEM_DYN);

    init_kernel<<<4000, 256>>>(hidden, cell, W_out, out);

    dim3 kvg(128, 4);
    kv_kernel<<<kvg, 256>>>(hs, Wk, bk, 0);
    kv_kernel<<<kvg, 256>>>(hs, Wv, bv, 1);

    decoder_persist<<<NCTA, 256, SMEM_DYN>>>(emb, W_ih, W_hh, b_ih, b_hh,
                                             Wq, bq, Wo, bo, W_out, b_out, out);
}